// round 17
// baseline (speedup 1.0000x reference)
#include <cuda_runtime.h>
#include <cstdint>

#define DINLINE __device__ __forceinline__

namespace {
constexpr int CIN = 512, PIX = 3136, NWIN = 8, WSTRIDE = 32;
constexpr int TM = 128;            // pixels per tile; 25 tiles, tile 24 half-valid
constexpr int NTILES = 25;
constexpr int NJOBS = 32 * NWIN * NTILES;  // 6400 jobs: (b, nwin, tile)
constexpr int NCTA = 296;          // 148 SMs x 2 CTAs (persistent)
constexpr int SPLIT = NJOBS - NCTA * (NJOBS / NCTA);
constexpr int JBASE = NJOBS / NCTA;
}

// W fragments (tf32-rounded fp32 bits), register order:
// idx = ng*2048 + ((ks*4 + j)*2 + r)*32 + lane
// n = ng*32 + j*8 + (lane>>2), k = ks*8 + (lane&3) + r*4
__device__ __align__(16) uint32_t g_wB[4096];

DINLINE uint32_t f2tf32(float f) {
    uint32_t r;
    asm("cvt.rna.tf32.f32 %0, %1;" : "=r"(r) : "f"(f));
    return r;
}

__global__ void prep_w(const float* __restrict__ w) {
    int t = threadIdx.x;
#pragma unroll
    for (int i = 0; i < 16; i++) {
        int idx  = i * 256 + t;
        int lane = idx & 31;
        int r    = (idx >> 5) & 1;
        int j    = (idx >> 6) & 3;
        int ks   = (idx >> 8) & 7;
        int ng   = (idx >> 11) & 1;
        int n = ng * 32 + j * 8 + (lane >> 2);
        int k = ks * 8 + (lane & 3) + r * 4;
        g_wB[idx] = f2tf32(w[n * 64 + k]);
    }
}

// load a gmem pixel-pair (two fp32) and apply half-ulp-of-tf32 bias in one IADD64.
// HMMA.TF32 truncates the low 13 register bits, so bias+truncate == RNA rounding.
DINLINE void ldgtf2(uint32_t& lo, uint32_t& hi, const float* p) {
    unsigned long long v = *reinterpret_cast<const unsigned long long*>(p);
    v += 0x0000100000001000ULL;
    lo = (uint32_t)v;
    hi = (uint32_t)(v >> 32);
}
DINLINE void mma_tf32(float* c, uint32_t a0, uint32_t a1, uint32_t a2, uint32_t a3,
                      uint32_t b0, uint32_t b1) {
    asm volatile(
        "mma.sync.aligned.m16n8k8.row.col.f32.tf32.tf32.f32 "
        "{%0,%1,%2,%3}, {%4,%5,%6,%7}, {%8,%9}, {%0,%1,%2,%3};"
        : "+f"(c[0]), "+f"(c[1]), "+f"(c[2]), "+f"(c[3])
        : "r"(a0), "r"(a1), "r"(a2), "r"(a3), "r"(b0), "r"(b1));
}

__global__ void __launch_bounds__(256, 2)
win_mma(const float* __restrict__ x, float* __restrict__ out) {
    const int t = threadIdx.x;
    const int lane = t & 31, w = t >> 5;
    const int mg = w & 3, ng = w >> 2;     // 4 M32-groups x 2 N32-groups

    // ---- B fragments: K=64, N=32 per warp, loaded ONCE per kernel ----
    uint32_t bw[8][4][2];
    {
        const uint32_t* base = g_wB + ng * 2048 + lane;
#pragma unroll
        for (int ks = 0; ks < 8; ks++)
#pragma unroll
            for (int j = 0; j < 4; j++)
#pragma unroll
                for (int r = 0; r < 2; r++)
                    bw[ks][j][r] = base[((ks * 4 + j) * 2 + r) * 32];
    }

    // persistent job range (contiguous chunk)
    const int c = blockIdx.x;
    const int jbeg = (c < SPLIT) ? c * (JBASE + 1) : c * JBASE + SPLIT;
    const int jend = jbeg + JBASE + (c < SPLIT ? 1 : 0);

    // A-fragment lane pieces; row->pixel map: row r -> px 2*(r&7) + (r>>3)
    const int grp = lane >> 2, tid4 = lane & 3;
    const int kA = tid4;                   // channel offset within k-step
    const int pxpair = mg * 32 + 2 * grp;  // + mf*16 (even local pixel)

    for (int i = jbeg; i < jend; i++) {
        const int tile = i % NTILES;
        const int rr = i / NTILES;
        const int nwin = rr & 7, b = rr >> 3;

        // base pointers: channel ch = nwin*WSTRIDE + ks*8 + kA (+4)
        const float* xb = x + ((size_t)(b * CIN + nwin * WSTRIDE + kA)) * PIX;

        // global pixel for each mf half (clamped for the tail tile; results
        // from clamped rows are discarded by the store guard)
        int gpx[2];
#pragma unroll
        for (int mf = 0; mf < 2; mf++) {
            int p = tile * TM + pxpair + mf * 16;
            gpx[mf] = (p + 1 < PIX) ? p : (PIX - 2);
        }

        // ---- MMA: warp tile M32 x N32, A straight from gmem (L1-cached) ----
        float acc[2][4][4];
#pragma unroll
        for (int mf = 0; mf < 2; mf++)
#pragma unroll
            for (int j = 0; j < 4; j++)
#pragma unroll
                for (int q = 0; q < 4; q++) acc[mf][j][q] = 0.0f;

        uint32_t A[2][4];   // double-buffered A fragments (segment s = ks*2 + mf)
        ldgtf2(A[0][0], A[0][1], xb + gpx[0]);
        ldgtf2(A[0][2], A[0][3], xb + (size_t)4 * PIX + gpx[0]);
#pragma unroll
        for (int s = 0; s < 16; s++) {       // ks = s>>1 (compile-time), mf = s&1
            const int mf = s & 1;
            const int ks = s >> 1;
            if (s < 15) {                    // prefetch next segment's A
                const int s1 = s + 1;
                const int ks1 = s1 >> 1;
                const float* p = xb + (size_t)(ks1 * 8) * PIX + gpx[s1 & 1];
                ldgtf2(A[s1 & 1][0], A[s1 & 1][1], p);
                ldgtf2(A[s1 & 1][2], A[s1 & 1][3], p + (size_t)4 * PIX);
            }
            const uint32_t* a = A[s & 1];
#pragma unroll
            for (int j = 0; j < 4; j++)
                mma_tf32(acc[mf][j], a[0], a[1], a[2], a[3], bw[ks][j][0], bw[ks][j][1]);
        }

        // ---- epilogue: paired STG.64 per (o, pixel-pair); guarded for tail ----
        float* ob = out + ((size_t)(b * CIN + nwin)) * PIX;
#pragma unroll
        for (int mf = 0; mf < 2; mf++) {
            const int px0 = tile * TM + pxpair + mf * 16;   // even; pair = px0, px0+1
            if (px0 + 1 < PIX) {
#pragma unroll
                for (int j = 0; j < 4; j++) {
                    int o = ng * 32 + j * 8 + tid4 * 2;
                    size_t s0 = (size_t)(o * NWIN) * PIX;
                    size_t s1 = s0 + (size_t)NWIN * PIX;
                    *(float2*)(ob + s0 + px0) = make_float2(acc[mf][j][0], acc[mf][j][2]);
                    *(float2*)(ob + s1 + px0) = make_float2(acc[mf][j][1], acc[mf][j][3]);
                }
            }
        }
    }
}

extern "C" void kernel_launch(void* const* d_in, const int* in_sizes, int n_in,
                              void* d_out, int out_size) {
    const float* x = (const float*)d_in[0];   // (32, 512, 56, 56) fp32
    const float* w = (const float*)d_in[1];   // (64, 64) fp32
    float* out = (float*)d_out;               // (32, 512, 56, 56) fp32

    prep_w<<<1, 256>>>(w);
    win_mma<<<NCTA, 256>>>(x, out);
}